// round 1
// baseline (speedup 1.0000x reference)
#include <cuda_runtime.h>
#include <math.h>

#define VOCAB 100000
#define HID 512
#define BATCH 4096
#define TOT 819200

// ---- scratch (no allocations allowed) ----
__device__ float g_pooled[BATCH * HID];        // 8 MB
__device__ float g_h[BATCH * HID];             // 8 MB
__device__ float g_part[128 * 2 * HID];        // 512 KB deterministic BN partials
__device__ float g_scale[HID];
__device__ float g_shift[HID];
__device__ int   g_off[BATCH + 1];

// ---------------------------------------------------------------------------
// Kernel 0: segment offsets. g_off[b] = first index i with segment_ids[i] >= b.
// segment_ids is sorted; handles empty segments (gaps) and tail.
// ---------------------------------------------------------------------------
__global__ void __launch_bounds__(256) offsets_kernel(const int* __restrict__ seg) {
    int i = blockIdx.x * blockDim.x + threadIdx.x;
    if (i >= TOT) return;
    int s = seg[i];
    if (i == 0) {
        for (int b = 0; b <= s; b++) g_off[b] = 0;
    } else {
        int p = seg[i - 1];
        for (int b = p + 1; b <= s; b++) g_off[b] = i;
    }
    if (i == TOT - 1) {
        for (int b = s + 1; b <= BATCH; b++) g_off[b] = TOT;
    }
}

// ---------------------------------------------------------------------------
// Kernel 1: gather + mean pool. One CTA per segment, 128 threads.
// Each thread accumulates a float4 slice of the 512-wide row.
// ---------------------------------------------------------------------------
__global__ void __launch_bounds__(128) pool_kernel(const int* __restrict__ tokens,
                                                   const float* __restrict__ emb) {
    int b = blockIdx.x;
    int start = g_off[b];
    int end   = g_off[b + 1];
    int j = threadIdx.x * 4;

    float4 acc = make_float4(0.f, 0.f, 0.f, 0.f);
    int i = start;
    for (; i + 4 <= end; i += 4) {
        int t0 = tokens[i], t1 = tokens[i + 1], t2 = tokens[i + 2], t3 = tokens[i + 3];
        float4 v0 = *reinterpret_cast<const float4*>(emb + (size_t)t0 * HID + j);
        float4 v1 = *reinterpret_cast<const float4*>(emb + (size_t)t1 * HID + j);
        float4 v2 = *reinterpret_cast<const float4*>(emb + (size_t)t2 * HID + j);
        float4 v3 = *reinterpret_cast<const float4*>(emb + (size_t)t3 * HID + j);
        acc.x += v0.x + v1.x + v2.x + v3.x;
        acc.y += v0.y + v1.y + v2.y + v3.y;
        acc.z += v0.z + v1.z + v2.z + v3.z;
        acc.w += v0.w + v1.w + v2.w + v3.w;
    }
    for (; i < end; i++) {
        int t0 = tokens[i];
        float4 v0 = *reinterpret_cast<const float4*>(emb + (size_t)t0 * HID + j);
        acc.x += v0.x; acc.y += v0.y; acc.z += v0.z; acc.w += v0.w;
    }
    float inv = 1.f / fmaxf((float)(end - start), 1.f);
    acc.x *= inv; acc.y *= inv; acc.z *= inv; acc.w *= inv;
    *reinterpret_cast<float4*>(g_pooled + (size_t)b * HID + j) = acc;
}

// ---------------------------------------------------------------------------
// Kernel 2: h = pooled @ W_h + b_h.  M=4096, N=512, K=512, fp32.
// BM=BN=128, BK=8, 256 threads, 8x8 microtile. Grid (32, 4).
// ---------------------------------------------------------------------------
__global__ void __launch_bounds__(256) gemm_kernel(const float* __restrict__ B,
                                                   const float* __restrict__ bias) {
    __shared__ float As[8][128];
    __shared__ float Bs[8][128];
    const float* A = g_pooled;
    int m0 = blockIdx.x * 128;
    int n0 = blockIdx.y * 128;
    int tid = threadIdx.x;
    int tx = tid & 15, ty = tid >> 4;

    int a_r = tid >> 1,  a_c = (tid & 1) * 4;     // A: 128 rows x 8 cols per tile
    int b_r = tid >> 5,  b_c = (tid & 31) * 4;    // B: 8 rows x 128 cols per tile

    float acc[8][8];
#pragma unroll
    for (int i = 0; i < 8; i++)
#pragma unroll
        for (int j = 0; j < 8; j++) acc[i][j] = 0.f;

    for (int k0 = 0; k0 < HID; k0 += 8) {
        float4 av = *reinterpret_cast<const float4*>(A + (size_t)(m0 + a_r) * HID + k0 + a_c);
        float4 bv = *reinterpret_cast<const float4*>(B + (size_t)(k0 + b_r) * HID + n0 + b_c);
        __syncthreads();
        As[a_c + 0][a_r] = av.x;
        As[a_c + 1][a_r] = av.y;
        As[a_c + 2][a_r] = av.z;
        As[a_c + 3][a_r] = av.w;
        *reinterpret_cast<float4*>(&Bs[b_r][b_c]) = bv;
        __syncthreads();
#pragma unroll
        for (int kk = 0; kk < 8; kk++) {
            float4 a0 = *reinterpret_cast<float4*>(&As[kk][ty * 8]);
            float4 a1 = *reinterpret_cast<float4*>(&As[kk][ty * 8 + 4]);
            float4 b0 = *reinterpret_cast<float4*>(&Bs[kk][tx * 8]);
            float4 b1 = *reinterpret_cast<float4*>(&Bs[kk][tx * 8 + 4]);
            float a[8] = {a0.x, a0.y, a0.z, a0.w, a1.x, a1.y, a1.z, a1.w};
            float bb[8] = {b0.x, b0.y, b0.z, b0.w, b1.x, b1.y, b1.z, b1.w};
#pragma unroll
            for (int i = 0; i < 8; i++)
#pragma unroll
                for (int j = 0; j < 8; j++) acc[i][j] += a[i] * bb[j];
        }
    }

#pragma unroll
    for (int i = 0; i < 8; i++) {
        int row = m0 + ty * 8 + i;
#pragma unroll
        for (int j = 0; j < 8; j += 4) {
            int col = n0 + tx * 8 + j;
            float4 o;
            o.x = acc[i][j + 0] + bias[col + 0];
            o.y = acc[i][j + 1] + bias[col + 1];
            o.z = acc[i][j + 2] + bias[col + 2];
            o.w = acc[i][j + 3] + bias[col + 3];
            *reinterpret_cast<float4*>(&g_h[(size_t)row * HID + col]) = o;
        }
    }
}

// ---------------------------------------------------------------------------
// Kernel 3: per-column sum/sumsq partials over 32-row chunks (deterministic).
// Grid 128 blocks x 256 threads; thread owns 2 columns (float2 loads).
// ---------------------------------------------------------------------------
__global__ void __launch_bounds__(256) stats_kernel() {
    int blk = blockIdx.x;
    int c = threadIdx.x * 2;
    int r0 = blk * 32;
    float s0 = 0.f, s1 = 0.f, q0 = 0.f, q1 = 0.f;
#pragma unroll 8
    for (int r = 0; r < 32; r++) {
        float2 v = *reinterpret_cast<const float2*>(&g_h[(size_t)(r0 + r) * HID + c]);
        s0 += v.x; s1 += v.y;
        q0 += v.x * v.x; q1 += v.y * v.y;
    }
    float* p = g_part + (size_t)blk * 2 * HID;
    p[c] = s0; p[c + 1] = s1;
    p[HID + c] = q0; p[HID + c + 1] = q1;
}

// ---------------------------------------------------------------------------
// Kernel 4: fold partials -> BN scale/shift per column.
// ---------------------------------------------------------------------------
__global__ void __launch_bounds__(512) finalize_kernel(const float* __restrict__ gamma,
                                                       const float* __restrict__ beta) {
    int c = threadIdx.x;
    float s = 0.f, q = 0.f;
    for (int i = 0; i < 128; i++) {
        const float* p = g_part + (size_t)i * 2 * HID;
        s += p[c];
        q += p[HID + c];
    }
    const float invN = 1.f / (float)BATCH;
    float mu  = s * invN;
    float var = q * invN - mu * mu;
    float sc  = gamma[c] * rsqrtf(var + 1e-5f);
    g_scale[c] = sc;
    g_shift[c] = beta[c] - mu * sc;
}

// ---------------------------------------------------------------------------
// Kernel 5: BN + ReLU + dot(W_o) + b_o -> logits. One CTA per row.
// ---------------------------------------------------------------------------
__global__ void __launch_bounds__(128) rowout_kernel(const float* __restrict__ Wo,
                                                     const float* __restrict__ bo,
                                                     float* __restrict__ out) {
    int row = blockIdx.x;
    int j = threadIdx.x * 4;
    float4 h4 = *reinterpret_cast<const float4*>(&g_h[(size_t)row * HID + j]);
    float4 sc = *reinterpret_cast<const float4*>(&g_scale[j]);
    float4 sh = *reinterpret_cast<const float4*>(&g_shift[j]);
    float4 w  = *reinterpret_cast<const float4*>(&Wo[j]);
    float y0 = fmaxf(h4.x * sc.x + sh.x, 0.f);
    float y1 = fmaxf(h4.y * sc.y + sh.y, 0.f);
    float y2 = fmaxf(h4.z * sc.z + sh.z, 0.f);
    float y3 = fmaxf(h4.w * sc.w + sh.w, 0.f);
    float p = y0 * w.x + y1 * w.y + y2 * w.z + y3 * w.w;
#pragma unroll
    for (int o = 16; o > 0; o >>= 1) p += __shfl_xor_sync(0xffffffffu, p, o);
    __shared__ float sp[4];
    if ((threadIdx.x & 31) == 0) sp[threadIdx.x >> 5] = p;
    __syncthreads();
    if (threadIdx.x == 0)
        out[1 + row] = sp[0] + sp[1] + sp[2] + sp[3] + bo[0];
}

// ---------------------------------------------------------------------------
// Kernel 6: loss = mean(softplus(x) - t*x) over 4096 logits -> out[0].
// ---------------------------------------------------------------------------
__global__ void __launch_bounds__(256) loss_kernel(const float* __restrict__ t,
                                                   float* __restrict__ out) {
    float s = 0.f;
    for (int i = threadIdx.x; i < BATCH; i += 256) {
        float x = out[1 + i];
        float sp = fmaxf(x, 0.f) + log1pf(expf(-fabsf(x)));
        s += sp - t[i] * x;
    }
#pragma unroll
    for (int o = 16; o > 0; o >>= 1) s += __shfl_xor_sync(0xffffffffu, s, o);
    __shared__ float sw[8];
    if ((threadIdx.x & 31) == 0) sw[threadIdx.x >> 5] = s;
    __syncthreads();
    if (threadIdx.x == 0) {
        float tot = 0.f;
        for (int i = 0; i < 8; i++) tot += sw[i];
        out[0] = tot * (1.f / (float)BATCH);
    }
}

// ---------------------------------------------------------------------------
extern "C" void kernel_launch(void* const* d_in, const int* in_sizes, int n_in,
                              void* d_out, int out_size) {
    const int*   tokens = (const int*)d_in[0];
    const int*   seg    = (const int*)d_in[1];
    const float* t      = (const float*)d_in[2];
    const float* emb    = (const float*)d_in[3];
    const float* Wh     = (const float*)d_in[4];
    const float* bh     = (const float*)d_in[5];
    const float* gamma  = (const float*)d_in[6];
    const float* beta   = (const float*)d_in[7];
    const float* Wo     = (const float*)d_in[8];
    const float* bo     = (const float*)d_in[9];
    float* out = (float*)d_out;

    offsets_kernel<<<(TOT + 255) / 256, 256>>>(seg);
    pool_kernel<<<BATCH, 128>>>(tokens, emb);
    dim3 gg(32, 4);
    gemm_kernel<<<gg, 256>>>(Wh, bh);
    stats_kernel<<<128, 256>>>();
    finalize_kernel<<<1, 512>>>(gamma, beta);
    rowout_kernel<<<BATCH, 128>>>(Wo, bo, out);
    loss_kernel<<<1, 256>>>(t, out);
}

// round 3
// speedup vs baseline: 1.4081x; 1.4081x over previous
#include <cuda_runtime.h>
#include <cuda_fp16.h>
#include <mma.h>
#include <math.h>

using namespace nvcuda;

#define VOCAB 100000
#define HID 512
#define BATCH 4096
#define TOT 819200

// ---- scratch (no allocations allowed) ----
__device__ __half g_emb_h[(size_t)VOCAB * HID];   // 102.4 MB fp16 table (fits L2)
__device__ float  g_pooled[BATCH * HID];          // 8 MB
__device__ float  g_h[BATCH * HID];               // 8 MB
__device__ float  g_part[128 * 2 * HID];          // BN partials (deterministic)
__device__ float  g_scale[HID];
__device__ float  g_shift[HID];
__device__ int    g_off[BATCH + 1];

// ---------------------------------------------------------------------------
// Kernel 0: emb fp32 -> fp16 (streaming).
// ---------------------------------------------------------------------------
__global__ void __launch_bounds__(256) conv_kernel(const float* __restrict__ emb) {
    const size_t n4 = (size_t)VOCAB * HID / 4;
    uint2* dst = reinterpret_cast<uint2*>(g_emb_h);
    const float4* src = reinterpret_cast<const float4*>(emb);
    for (size_t idx = (size_t)blockIdx.x * blockDim.x + threadIdx.x; idx < n4;
         idx += (size_t)gridDim.x * blockDim.x) {
        float4 v = src[idx];
        __half2 a = __floats2half2_rn(v.x, v.y);
        __half2 b = __floats2half2_rn(v.z, v.w);
        uint2 o;
        o.x = *reinterpret_cast<unsigned*>(&a);
        o.y = *reinterpret_cast<unsigned*>(&b);
        dst[idx] = o;
    }
}

// ---------------------------------------------------------------------------
// Kernel 1: segment offsets from sorted segment_ids (handles gaps + tail).
// ---------------------------------------------------------------------------
__global__ void __launch_bounds__(256) offsets_kernel(const int* __restrict__ seg) {
    int i = blockIdx.x * blockDim.x + threadIdx.x;
    if (i >= TOT) return;
    int s = seg[i];
    if (i == 0) {
        for (int b = 0; b <= s; b++) g_off[b] = 0;
    } else {
        int p = seg[i - 1];
        for (int b = p + 1; b <= s; b++) g_off[b] = i;
    }
    if (i == TOT - 1) {
        for (int b = s + 1; b <= BATCH; b++) g_off[b] = TOT;
    }
}

// ---------------------------------------------------------------------------
// Kernel 2: gather + mean pool from fp16 table. One CTA (256 thr) per segment.
// 4 token-groups of 64 threads; each thread loads one uint4 (8 halfs) per token.
// ---------------------------------------------------------------------------
__global__ void __launch_bounds__(256) pool_kernel(const int* __restrict__ tokens) {
    int b = blockIdx.x;
    int start = g_off[b];
    int end   = g_off[b + 1];
    int g    = threadIdx.x >> 6;   // 0..3
    int lane = threadIdx.x & 63;   // 0..63 -> halfs [lane*8, lane*8+8)

    float acc0[8], acc1[8];
#pragma unroll
    for (int k = 0; k < 8; k++) { acc0[k] = 0.f; acc1[k] = 0.f; }

    int i = start + g;
    for (; i + 4 < end; i += 8) {
        int t0 = tokens[i];
        int t1 = tokens[i + 4];
        uint4 v0 = reinterpret_cast<const uint4*>(g_emb_h + (size_t)t0 * HID)[lane];
        uint4 v1 = reinterpret_cast<const uint4*>(g_emb_h + (size_t)t1 * HID)[lane];
        const __half2* p0 = reinterpret_cast<const __half2*>(&v0);
        const __half2* p1 = reinterpret_cast<const __half2*>(&v1);
#pragma unroll
        for (int w = 0; w < 4; w++) {
            float2 f0 = __half22float2(p0[w]);
            float2 f1 = __half22float2(p1[w]);
            acc0[w * 2 + 0] += f0.x; acc0[w * 2 + 1] += f0.y;
            acc1[w * 2 + 0] += f1.x; acc1[w * 2 + 1] += f1.y;
        }
    }
    if (i < end) {
        int t0 = tokens[i];
        uint4 v0 = reinterpret_cast<const uint4*>(g_emb_h + (size_t)t0 * HID)[lane];
        const __half2* p0 = reinterpret_cast<const __half2*>(&v0);
#pragma unroll
        for (int w = 0; w < 4; w++) {
            float2 f0 = __half22float2(p0[w]);
            acc0[w * 2 + 0] += f0.x; acc0[w * 2 + 1] += f0.y;
        }
    }
#pragma unroll
    for (int k = 0; k < 8; k++) acc0[k] += acc1[k];

    __shared__ float red[4][HID];
#pragma unroll
    for (int k = 0; k < 8; k++) red[g][lane * 8 + k] = acc0[k];
    __syncthreads();

    if (g == 0) {
        float inv = 1.f / fmaxf((float)(end - start), 1.f);
        float o[8];
#pragma unroll
        for (int k = 0; k < 8; k++) {
            int c = lane * 8 + k;
            o[k] = (red[0][c] + red[1][c] + red[2][c] + red[3][c]) * inv;
        }
        float4* dst = reinterpret_cast<float4*>(g_pooled + (size_t)b * HID + lane * 8);
        dst[0] = make_float4(o[0], o[1], o[2], o[3]);
        dst[1] = make_float4(o[4], o[5], o[6], o[7]);
    }
}

// ---------------------------------------------------------------------------
// Kernel 3: h = pooled @ W_h  (b_h dropped: BatchNorm subtracts the batch mean,
// so a per-column bias is a mathematical no-op). tf32 wmma, fp32 accumulate.
// CTA tile 128x64, 8 warps (4x2), warp tile 32x32, BK=32. Grid (32, 8).
// ---------------------------------------------------------------------------
__global__ void __launch_bounds__(256) gemm_kernel(const float* __restrict__ B) {
    __shared__ float As[128][36];
    __shared__ float Bs[32][68];
    const float* A = g_pooled;
    int m0 = blockIdx.x * 128;
    int n0 = blockIdx.y * 64;
    int tid = threadIdx.x;
    int warp = tid >> 5;
    int wm = warp & 3;
    int wn = warp >> 2;

    wmma::fragment<wmma::accumulator, 16, 16, 8, float> acc[2][2];
#pragma unroll
    for (int i = 0; i < 2; i++)
#pragma unroll
        for (int j = 0; j < 2; j++) wmma::fill_fragment(acc[i][j], 0.f);

    for (int k0 = 0; k0 < HID; k0 += 32) {
        __syncthreads();
#pragma unroll
        for (int x = tid; x < 1024; x += 256) {
            int r = x >> 3, c = (x & 7) << 2;
            float4 v = *reinterpret_cast<const float4*>(A + (size_t)(m0 + r) * HID + k0 + c);
            *reinterpret_cast<float4*>(&As[r][c]) = v;
        }
#pragma unroll
        for (int x = tid; x < 512; x += 256) {
            int r = x >> 4, c = (x & 15) << 2;
            float4 v = *reinterpret_cast<const float4*>(B + (size_t)(k0 + r) * HID + n0 + c);
            *reinterpret_cast<float4*>(&Bs[r][c]) = v;
        }
        __syncthreads();
#pragma unroll
        for (int kk = 0; kk < 32; kk += 8) {
            wmma::fragment<wmma::matrix_a, 16, 16, 8, wmma::precision::tf32, wmma::row_major> af[2];
            wmma::fragment<wmma::matrix_b, 16, 16, 8, wmma::precision::tf32, wmma::row_major> bf[2];
#pragma unroll
            for (int i = 0; i < 2; i++) {
                wmma::load_matrix_sync(af[i], &As[wm * 32 + i * 16][kk], 36);
#pragma unroll
                for (int e = 0; e < af[i].num_elements; e++)
                    af[i].x[e] = wmma::__float_to_tf32(af[i].x[e]);
            }
#pragma unroll
            for (int j = 0; j < 2; j++) {
                wmma::load_matrix_sync(bf[j], &Bs[kk][wn * 32 + j * 16], 68);
#pragma unroll
                for (int e = 0; e < bf[j].num_elements; e++)
                    bf[j].x[e] = wmma::__float_to_tf32(bf[j].x[e]);
            }
#pragma unroll
            for (int i = 0; i < 2; i++)
#pragma unroll
                for (int j = 0; j < 2; j++)
                    wmma::mma_sync(acc[i][j], af[i], bf[j], acc[i][j]);
        }
    }
#pragma unroll
    for (int i = 0; i < 2; i++)
#pragma unroll
        for (int j = 0; j < 2; j++)
            wmma::store_matrix_sync(g_h + (size_t)(m0 + wm * 32 + i * 16) * HID
                                        + n0 + wn * 32 + j * 16,
                                    acc[i][j], HID, wmma::mem_row_major);
}

// ---------------------------------------------------------------------------
// Kernel 4: per-column sum/sumsq partials over 32-row chunks (deterministic).
// ---------------------------------------------------------------------------
__global__ void __launch_bounds__(256) stats_kernel() {
    int blk = blockIdx.x;
    int c = threadIdx.x * 2;
    int r0 = blk * 32;
    float s0 = 0.f, s1 = 0.f, q0 = 0.f, q1 = 0.f;
#pragma unroll 8
    for (int r = 0; r < 32; r++) {
        float2 v = *reinterpret_cast<const float2*>(&g_h[(size_t)(r0 + r) * HID + c]);
        s0 += v.x; s1 += v.y;
        q0 += v.x * v.x; q1 += v.y * v.y;
    }
    float* p = g_part + (size_t)blk * 2 * HID;
    p[c] = s0; p[c + 1] = s1;
    p[HID + c] = q0; p[HID + c + 1] = q1;
}

// ---------------------------------------------------------------------------
// Kernel 5: fold partials -> BN scale/shift per column.
// ---------------------------------------------------------------------------
__global__ void __launch_bounds__(512) finalize_kernel(const float* __restrict__ gamma,
                                                       const float* __restrict__ beta) {
    int c = threadIdx.x;
    float s = 0.f, q = 0.f;
    for (int i = 0; i < 128; i++) {
        const float* p = g_part + (size_t)i * 2 * HID;
        s += p[c];
        q += p[HID + c];
    }
    const float invN = 1.f / (float)BATCH;
    float mu  = s * invN;
    float var = q * invN - mu * mu;
    float sc  = gamma[c] * rsqrtf(var + 1e-5f);
    g_scale[c] = sc;
    g_shift[c] = beta[c] - mu * sc;
}

// ---------------------------------------------------------------------------
// Kernel 6: BN + ReLU + dot(W_o) + b_o -> logits. One CTA per row.
// ---------------------------------------------------------------------------
__global__ void __launch_bounds__(128) rowout_kernel(const float* __restrict__ Wo,
                                                     const float* __restrict__ bo,
                                                     float* __restrict__ out) {
    int row = blockIdx.x;
    int j = threadIdx.x * 4;
    float4 h4 = *reinterpret_cast<const float4*>(&g_h[(size_t)row * HID + j]);
    float4 sc = *reinterpret_cast<const float4*>(&g_scale[j]);
    float4 sh = *reinterpret_cast<const float4*>(&g_shift[j]);
    float4 w  = *reinterpret_cast<const float4*>(&Wo[j]);
    float y0 = fmaxf(h4.x * sc.x + sh.x, 0.f);
    float y1 = fmaxf(h4.y * sc.y + sh.y, 0.f);
    float y2 = fmaxf(h4.z * sc.z + sh.z, 0.f);
    float y3 = fmaxf(h4.w * sc.w + sh.w, 0.f);
    float p = y0 * w.x + y1 * w.y + y2 * w.z + y3 * w.w;
#pragma unroll
    for (int o = 16; o > 0; o >>= 1) p += __shfl_xor_sync(0xffffffffu, p, o);
    __shared__ float sp[4];
    if ((threadIdx.x & 31) == 0) sp[threadIdx.x >> 5] = p;
    __syncthreads();
    if (threadIdx.x == 0)
        out[1 + row] = sp[0] + sp[1] + sp[2] + sp[3] + bo[0];
}

// ---------------------------------------------------------------------------
// Kernel 7: loss = mean(softplus(x) - t*x) -> out[0].
// ---------------------------------------------------------------------------
__global__ void __launch_bounds__(256) loss_kernel(const float* __restrict__ t,
                                                   float* __restrict__ out) {
    float s = 0.f;
    for (int i = threadIdx.x; i < BATCH; i += 256) {
        float x = out[1 + i];
        float sp = fmaxf(x, 0.f) + log1pf(expf(-fabsf(x)));
        s += sp - t[i] * x;
    }
#pragma unroll
    for (int o = 16; o > 0; o >>= 1) s += __shfl_xor_sync(0xffffffffu, s, o);
    __shared__ float sw[8];
    if ((threadIdx.x & 31) == 0) sw[threadIdx.x >> 5] = s;
    __syncthreads();
    if (threadIdx.x == 0) {
        float tot = 0.f;
        for (int i = 0; i < 8; i++) tot += sw[i];
        out[0] = tot * (1.f / (float)BATCH);
    }
}

// ---------------------------------------------------------------------------
extern "C" void kernel_launch(void* const* d_in, const int* in_sizes, int n_in,
                              void* d_out, int out_size) {
    const int*   tokens = (const int*)d_in[0];
    const int*   seg    = (const int*)d_in[1];
    const float* t      = (const float*)d_in[2];
    const float* emb    = (const float*)d_in[3];
    const float* Wh     = (const float*)d_in[4];
    const float* gamma  = (const float*)d_in[6];
    const float* beta   = (const float*)d_in[7];
    const float* Wo     = (const float*)d_in[8];
    const float* bo     = (const float*)d_in[9];
    float* out = (float*)d_out;

    conv_kernel<<<1184, 256>>>(emb);
    offsets_kernel<<<(TOT + 255) / 256, 256>>>(seg);
    pool_kernel<<<BATCH, 256>>>(tokens);
    dim3 gg(32, 8);
    gemm_kernel<<<gg, 256>>>(Wh);
    stats_kernel<<<128, 256>>>();
    finalize_kernel<<<1, 512>>>(gamma, beta);
    rowout_kernel<<<BATCH, 128>>>(Wo, bo, out);
    loss_kernel<<<1, 256>>>(t, out);
}

// round 4
// speedup vs baseline: 1.4233x; 1.0108x over previous
#include <cuda_runtime.h>
#include <cuda_fp16.h>
#include <mma.h>
#include <math.h>

using namespace nvcuda;

#define VOCAB 100000
#define HID 512
#define BATCH 4096
#define TOT 819200

// ---- scratch (no allocations allowed) ----
__device__ __half g_emb_h[(size_t)VOCAB * HID];   // 102.4 MB fp16 table (fits L2)
__device__ float  g_pooled[BATCH * HID];          // 8 MB
__device__ float  g_h[BATCH * HID];               // 8 MB
__device__ float  g_part[32 * 2 * HID];           // per-m-block BN partials
__device__ float  g_scale[HID];
__device__ float  g_shift[HID];
__device__ int    g_off[BATCH + 1];

// ---------------------------------------------------------------------------
// Kernel 0: emb fp32 -> fp16 (streaming). 16B stores.
// ---------------------------------------------------------------------------
__global__ void __launch_bounds__(256) conv_kernel(const float* __restrict__ emb) {
    const size_t n8 = (size_t)VOCAB * HID / 8;
    uint4* dst = reinterpret_cast<uint4*>(g_emb_h);
    const float4* src = reinterpret_cast<const float4*>(emb);
    for (size_t idx = (size_t)blockIdx.x * blockDim.x + threadIdx.x; idx < n8;
         idx += (size_t)gridDim.x * blockDim.x) {
        float4 v0 = src[idx * 2];
        float4 v1 = src[idx * 2 + 1];
        __half2 a = __floats2half2_rn(v0.x, v0.y);
        __half2 b = __floats2half2_rn(v0.z, v0.w);
        __half2 c = __floats2half2_rn(v1.x, v1.y);
        __half2 d = __floats2half2_rn(v1.z, v1.w);
        uint4 o;
        o.x = *reinterpret_cast<unsigned*>(&a);
        o.y = *reinterpret_cast<unsigned*>(&b);
        o.z = *reinterpret_cast<unsigned*>(&c);
        o.w = *reinterpret_cast<unsigned*>(&d);
        dst[idx] = o;
    }
}

// ---------------------------------------------------------------------------
// Kernel 1: segment offsets from sorted segment_ids (handles gaps + tail).
// ---------------------------------------------------------------------------
__global__ void __launch_bounds__(256) offsets_kernel(const int* __restrict__ seg) {
    int i = blockIdx.x * blockDim.x + threadIdx.x;
    if (i >= TOT) return;
    int s = seg[i];
    if (i == 0) {
        for (int b = 0; b <= s; b++) g_off[b] = 0;
    } else {
        int p = seg[i - 1];
        for (int b = p + 1; b <= s; b++) g_off[b] = i;
    }
    if (i == TOT - 1) {
        for (int b = s + 1; b <= BATCH; b++) g_off[b] = TOT;
    }
}

// ---------------------------------------------------------------------------
// Kernel 2: gather + mean pool from fp16 table. One CTA (256 thr) per segment.
// ---------------------------------------------------------------------------
__global__ void __launch_bounds__(256) pool_kernel(const int* __restrict__ tokens) {
    int b = blockIdx.x;
    int start = g_off[b];
    int end   = g_off[b + 1];
    int g    = threadIdx.x >> 6;   // 0..3
    int lane = threadIdx.x & 63;   // 0..63 -> halfs [lane*8, lane*8+8)

    float acc0[8], acc1[8];
#pragma unroll
    for (int k = 0; k < 8; k++) { acc0[k] = 0.f; acc1[k] = 0.f; }

    int i = start + g;
    for (; i + 4 < end; i += 8) {
        int t0 = tokens[i];
        int t1 = tokens[i + 4];
        uint4 v0 = reinterpret_cast<const uint4*>(g_emb_h + (size_t)t0 * HID)[lane];
        uint4 v1 = reinterpret_cast<const uint4*>(g_emb_h + (size_t)t1 * HID)[lane];
        const __half2* p0 = reinterpret_cast<const __half2*>(&v0);
        const __half2* p1 = reinterpret_cast<const __half2*>(&v1);
#pragma unroll
        for (int w = 0; w < 4; w++) {
            float2 f0 = __half22float2(p0[w]);
            float2 f1 = __half22float2(p1[w]);
            acc0[w * 2 + 0] += f0.x; acc0[w * 2 + 1] += f0.y;
            acc1[w * 2 + 0] += f1.x; acc1[w * 2 + 1] += f1.y;
        }
    }
    if (i < end) {
        int t0 = tokens[i];
        uint4 v0 = reinterpret_cast<const uint4*>(g_emb_h + (size_t)t0 * HID)[lane];
        const __half2* p0 = reinterpret_cast<const __half2*>(&v0);
#pragma unroll
        for (int w = 0; w < 4; w++) {
            float2 f0 = __half22float2(p0[w]);
            acc0[w * 2 + 0] += f0.x; acc0[w * 2 + 1] += f0.y;
        }
    }
#pragma unroll
    for (int k = 0; k < 8; k++) acc0[k] += acc1[k];

    __shared__ float red[4][HID];
#pragma unroll
    for (int k = 0; k < 8; k++) red[g][lane * 8 + k] = acc0[k];
    __syncthreads();

    if (g == 0) {
        float inv = 1.f / fmaxf((float)(end - start), 1.f);
        float o[8];
#pragma unroll
        for (int k = 0; k < 8; k++) {
            int c = lane * 8 + k;
            o[k] = (red[0][c] + red[1][c] + red[2][c] + red[3][c]) * inv;
        }
        float4* dst = reinterpret_cast<float4*>(g_pooled + (size_t)b * HID + lane * 8);
        dst[0] = make_float4(o[0], o[1], o[2], o[3]);
        dst[1] = make_float4(o[4], o[5], o[6], o[7]);
    }
}

// ---------------------------------------------------------------------------
// Kernel 3: h = pooled @ W_h (b_h dropped: no-op through BatchNorm).
// tf32 wmma, fp32 accum. CTA tile 128x128, BK=16, double-buffered SMEM,
// tf32 conversion at staging. 8 warps (2m x 4n), warp tile 64x32.
// Grid (32, 4) = 128 CTAs (single wave). Fused BN column partials in epilogue.
// ---------------------------------------------------------------------------
#define BK 16
__global__ void __launch_bounds__(256) gemm_kernel(const float* __restrict__ B) {
    __shared__ float As[2][128][BK + 4];   // stride 20 (80B, 16B-aligned rows)
    __shared__ float Bs[2][BK][128 + 4];   // stride 132 (528B, 16B-aligned rows)
    __shared__ float s2[2][2][128];        // fused-stats halves

    const float* A = g_pooled;
    int m0 = blockIdx.x * 128;
    int n0 = blockIdx.y * 128;
    int tid = threadIdx.x;
    int warp = tid >> 5;
    int wm = warp >> 2;        // 0..1  -> m offset wm*64
    int wn = warp & 3;         // 0..3  -> n offset wn*32

    // staging indices: A tile 128x16 = 512 float4, 2 per thread
    int a_r0 = tid >> 2, a_c0 = (tid & 3) << 2;            // rows 0..63
    // second: rows 64..127 same pattern
    // B tile 16x128 = 512 float4, 2 per thread
    int b_r0 = tid >> 5, b_c0 = (tid & 31) << 2;           // rows 0..7
    // second: rows 8..15

    wmma::fragment<wmma::accumulator, 16, 16, 8, float> acc[4][2];
#pragma unroll
    for (int i = 0; i < 4; i++)
#pragma unroll
        for (int j = 0; j < 2; j++) wmma::fill_fragment(acc[i][j], 0.f);

    auto cvt4 = [](float4 v) {
        v.x = wmma::__float_to_tf32(v.x);
        v.y = wmma::__float_to_tf32(v.y);
        v.z = wmma::__float_to_tf32(v.z);
        v.w = wmma::__float_to_tf32(v.w);
        return v;
    };

    // prologue: load tile 0 into buffer 0
    {
        float4 a0 = *reinterpret_cast<const float4*>(A + (size_t)(m0 + a_r0) * HID + a_c0);
        float4 a1 = *reinterpret_cast<const float4*>(A + (size_t)(m0 + 64 + a_r0) * HID + a_c0);
        float4 b0 = *reinterpret_cast<const float4*>(B + (size_t)b_r0 * HID + n0 + b_c0);
        float4 b1 = *reinterpret_cast<const float4*>(B + (size_t)(8 + b_r0) * HID + n0 + b_c0);
        *reinterpret_cast<float4*>(&As[0][a_r0][a_c0])      = cvt4(a0);
        *reinterpret_cast<float4*>(&As[0][64 + a_r0][a_c0]) = cvt4(a1);
        *reinterpret_cast<float4*>(&Bs[0][b_r0][b_c0])      = cvt4(b0);
        *reinterpret_cast<float4*>(&Bs[0][8 + b_r0][b_c0])  = cvt4(b1);
    }
    __syncthreads();

    const int NT = HID / BK;   // 32
    float4 pa0, pa1, pb0, pb1;
    for (int k0 = 0; k0 < NT; k0++) {
        int cur = k0 & 1;
        if (k0 + 1 < NT) {
            int kb = (k0 + 1) * BK;
            pa0 = *reinterpret_cast<const float4*>(A + (size_t)(m0 + a_r0) * HID + kb + a_c0);
            pa1 = *reinterpret_cast<const float4*>(A + (size_t)(m0 + 64 + a_r0) * HID + kb + a_c0);
            pb0 = *reinterpret_cast<const float4*>(B + (size_t)(kb + b_r0) * HID + n0 + b_c0);
            pb1 = *reinterpret_cast<const float4*>(B + (size_t)(kb + 8 + b_r0) * HID + n0 + b_c0);
        }
#pragma unroll
        for (int kk = 0; kk < 2; kk++) {
            wmma::fragment<wmma::matrix_a, 16, 16, 8, wmma::precision::tf32, wmma::row_major> af[4];
            wmma::fragment<wmma::matrix_b, 16, 16, 8, wmma::precision::tf32, wmma::row_major> bf[2];
#pragma unroll
            for (int i = 0; i < 4; i++)
                wmma::load_matrix_sync(af[i], &As[cur][wm * 64 + i * 16][kk * 8], BK + 4);
#pragma unroll
            for (int j = 0; j < 2; j++)
                wmma::load_matrix_sync(bf[j], &Bs[cur][kk * 8][wn * 32 + j * 16], 132);
#pragma unroll
            for (int i = 0; i < 4; i++)
#pragma unroll
                for (int j = 0; j < 2; j++)
                    wmma::mma_sync(acc[i][j], af[i], bf[j], acc[i][j]);
        }
        if (k0 + 1 < NT) {
            int nxt = cur ^ 1;
            *reinterpret_cast<float4*>(&As[nxt][a_r0][a_c0])      = cvt4(pa0);
            *reinterpret_cast<float4*>(&As[nxt][64 + a_r0][a_c0]) = cvt4(pa1);
            *reinterpret_cast<float4*>(&Bs[nxt][b_r0][b_c0])      = cvt4(pb0);
            *reinterpret_cast<float4*>(&Bs[nxt][8 + b_r0][b_c0])  = cvt4(pb1);
        }
        __syncthreads();
    }

    // write h tile
#pragma unroll
    for (int i = 0; i < 4; i++)
#pragma unroll
        for (int j = 0; j < 2; j++)
            wmma::store_matrix_sync(g_h + (size_t)(m0 + wm * 64 + i * 16) * HID
                                        + n0 + wn * 32 + j * 16,
                                    acc[i][j], HID, wmma::mem_row_major);
    __syncthreads();   // block-scope fence: tile writes visible to block

    // fused BN partials: re-read own tile (L2-hot), column sum/sumsq
    {
        int c    = tid & 127;
        int half = tid >> 7;          // 0: rows 0..63, 1: rows 64..127
        float s = 0.f, q = 0.f;
        const float* col = g_h + (size_t)(m0 + half * 64) * HID + n0 + c;
#pragma unroll 8
        for (int r = 0; r < 64; r++) {
            float v = col[(size_t)r * HID];
            s += v; q += v * v;
        }
        s2[half][0][c] = s;
        s2[half][1][c] = q;
        __syncthreads();
        if (half == 0) {
            float* p = g_part + (size_t)blockIdx.x * 2 * HID + n0;
            p[c]       = s2[0][0][c] + s2[1][0][c];
            p[HID + c] = s2[0][1][c] + s2[1][1][c];
        }
    }
}

// ---------------------------------------------------------------------------
// Kernel 4: fold 32 partials -> BN scale/shift per column.
// ---------------------------------------------------------------------------
__global__ void __launch_bounds__(512) finalize_kernel(const float* __restrict__ gamma,
                                                       const float* __restrict__ beta) {
    int c = threadIdx.x;
    float s = 0.f, q = 0.f;
    for (int i = 0; i < 32; i++) {
        const float* p = g_part + (size_t)i * 2 * HID;
        s += p[c];
        q += p[HID + c];
    }
    const float invN = 1.f / (float)BATCH;
    float mu  = s * invN;
    float var = q * invN - mu * mu;
    float sc  = gamma[c] * rsqrtf(var + 1e-5f);
    g_scale[c] = sc;
    g_shift[c] = beta[c] - mu * sc;
}

// ---------------------------------------------------------------------------
// Kernel 5: BN + ReLU + dot(W_o) + b_o -> logits. One CTA per row.
// ---------------------------------------------------------------------------
__global__ void __launch_bounds__(128) rowout_kernel(const float* __restrict__ Wo,
                                                     const float* __restrict__ bo,
                                                     float* __restrict__ out) {
    int row = blockIdx.x;
    int j = threadIdx.x * 4;
    float4 h4 = *reinterpret_cast<const float4*>(&g_h[(size_t)row * HID + j]);
    float4 sc = *reinterpret_cast<const float4*>(&g_scale[j]);
    float4 sh = *reinterpret_cast<const float4*>(&g_shift[j]);
    float4 w  = *reinterpret_cast<const float4*>(&Wo[j]);
    float y0 = fmaxf(h4.x * sc.x + sh.x, 0.f);
    float y1 = fmaxf(h4.y * sc.y + sh.y, 0.f);
    float y2 = fmaxf(h4.z * sc.z + sh.z, 0.f);
    float y3 = fmaxf(h4.w * sc.w + sh.w, 0.f);
    float p = y0 * w.x + y1 * w.y + y2 * w.z + y3 * w.w;
#pragma unroll
    for (int o = 16; o > 0; o >>= 1) p += __shfl_xor_sync(0xffffffffu, p, o);
    __shared__ float sp[4];
    if ((threadIdx.x & 31) == 0) sp[threadIdx.x >> 5] = p;
    __syncthreads();
    if (threadIdx.x == 0)
        out[1 + row] = sp[0] + sp[1] + sp[2] + sp[3] + bo[0];
}

// ---------------------------------------------------------------------------
// Kernel 6: loss = mean(softplus(x) - t*x) -> out[0].
// ---------------------------------------------------------------------------
__global__ void __launch_bounds__(256) loss_kernel(const float* __restrict__ t,
                                                   float* __restrict__ out) {
    float s = 0.f;
    for (int i = threadIdx.x; i < BATCH; i += 256) {
        float x = out[1 + i];
        float sp = fmaxf(x, 0.f) + log1pf(expf(-fabsf(x)));
        s += sp - t[i] * x;
    }
#pragma unroll
    for (int o = 16; o > 0; o >>= 1) s += __shfl_xor_sync(0xffffffffu, s, o);
    __shared__ float sw[8];
    if ((threadIdx.x & 31) == 0) sw[threadIdx.x >> 5] = s;
    __syncthreads();
    if (threadIdx.x == 0) {
        float tot = 0.f;
        for (int i = 0; i < 8; i++) tot += sw[i];
        out[0] = tot * (1.f / (float)BATCH);
    }
}

// ---------------------------------------------------------------------------
extern "C" void kernel_launch(void* const* d_in, const int* in_sizes, int n_in,
                              void* d_out, int out_size) {
    const int*   tokens = (const int*)d_in[0];
    const int*   seg    = (const int*)d_in[1];
    const float* t      = (const float*)d_in[2];
    const float* emb    = (const float*)d_in[3];
    const float* Wh     = (const float*)d_in[4];
    const float* gamma  = (const float*)d_in[6];
    const float* beta   = (const float*)d_in[7];
    const float* Wo     = (const float*)d_in[8];
    const float* bo     = (const float*)d_in[9];
    float* out = (float*)d_out;

    conv_kernel<<<1184, 256>>>(emb);
    offsets_kernel<<<(TOT + 255) / 256, 256>>>(seg);
    pool_kernel<<<BATCH, 256>>>(tokens);
    dim3 gg(32, 4);
    gemm_kernel<<<gg, 256>>>(Wh);
    finalize_kernel<<<1, 512>>>(gamma, beta);
    rowout_kernel<<<BATCH, 128>>>(Wo, bo, out);
    loss_kernel<<<1, 256>>>(t, out);
}